// round 12
// baseline (speedup 1.0000x reference)
#include <cuda_runtime.h>
#include <cuda_fp16.h>
#include <cstdint>
#include <math.h>

// KMeansClusteringLoss, R12: 2 independent CTAs per SM (split barrier domains).
//   cost(l,c) = |mu_c|^2 - 2 <z_l, mu_c>,  d(l) = sqrt(max(|z_l|^2 + min_c cost, 0))
//   out = mean_l d(l)
//
// Each CTA owns HALF the centroids (256) in smem and streams z tiles (64 rows)
// against them with fp16 HMMA. Per-point min across the two halves is combined
// in global memory via atomicMax on a monotone encoding (~bits of d^2, identity
// 0 == zero-init). Phase 2 (same kernel): grid-wide spin, sliced sqrt+sum, last
// CTA writes the mean and self-cleans all globals for graph replay.

#define KDIM  128
#define CDIM  512
#define MT    64
#define THREADS 256
#define NLOC  256          // centroids per CTA (one half)

#define STRIDE_B 272       // 128 f16 (256B) + 16B pad -> conflict-free LDSM

// dynamic smem layout (bytes)
#define SM_MU   0                           // 256 x 272 = 69632
#define SM_Z    69632                       // 64 x 272  = 17408
#define SM_M2   87040                       // 256 f32
#define SM_Z2   88064                       // 64 f32
#define SM_MH   88320                       // 64 x 2 f32
#define SM_PT   88832                       // 2 ints
#define SM_RED  88840                       // 8 f32
#define SMEM_BYTES 88896

__device__ float g_sum;                    // zero-init; self-cleaned
__device__ unsigned int g_cnt;
__device__ unsigned int g_cnt2;
__device__ unsigned int g_tile2[2];        // steal counters per centroid-half
__device__ unsigned int g_enc[65536];      // per-point min-d^2, ~bits encoding

// ---------------- helpers ----------------
__device__ __forceinline__ uint32_t smem_u32(const void* p) {
    uint32_t a;
    asm("{ .reg .u64 t; cvta.to.shared.u64 t, %1; cvt.u32.u64 %0, t; }" : "=r"(a) : "l"(p));
    return a;
}
__device__ __forceinline__ void ldsm_x4(uint32_t& r0, uint32_t& r1, uint32_t& r2, uint32_t& r3,
                                        uint32_t addr) {
    asm volatile("ldmatrix.sync.aligned.m8n8.x4.shared.b16 {%0,%1,%2,%3}, [%4];"
                 : "=r"(r0), "=r"(r1), "=r"(r2), "=r"(r3) : "r"(addr));
}
// f16 x f16 -> f16 accum. d0 = (row g, cols 2tg..), d1 = (row g+8).
__device__ __forceinline__ void mma_f16(uint32_t& d0, uint32_t& d1, const uint32_t* a,
                                        uint32_t b0, uint32_t b1) {
    asm volatile(
        "mma.sync.aligned.m16n8k16.row.col.f16.f16.f16.f16 "
        "{%0,%1}, {%2,%3,%4,%5}, {%6,%7}, {%0,%1};"
        : "+r"(d0), "+r"(d1)
        : "r"(a[0]), "r"(a[1]), "r"(a[2]), "r"(a[3]), "r"(b0), "r"(b1));
}

__device__ __forceinline__ void cvt_sts(const float4& v0, const float4& v1, char* dst) {
    __half2 h0 = __floats2half2_rn(v0.x, v0.y);
    __half2 h1 = __floats2half2_rn(v0.z, v0.w);
    __half2 h2 = __floats2half2_rn(v1.x, v1.y);
    __half2 h3 = __floats2half2_rn(v1.z, v1.w);
    uint4 q;
    q.x = *reinterpret_cast<uint32_t*>(&h0);
    q.y = *reinterpret_cast<uint32_t*>(&h1);
    q.z = *reinterpret_cast<uint32_t*>(&h2);
    q.w = *reinterpret_cast<uint32_t*>(&h3);
    *reinterpret_cast<uint4*>(dst) = q;
}

// ---------------- persistent kernel ----------------
__global__ void __launch_bounds__(THREADS, 2) km_main(
    const float* __restrict__ z, const float* __restrict__ mu,
    float* __restrict__ out, int L, int ntiles, int grid)
{
    extern __shared__ char smem[];
    const uint32_t sbase = smem_u32(smem);
    float* m2s = reinterpret_cast<float*>(smem + SM_M2);
    float* z2s = reinterpret_cast<float*>(smem + SM_Z2);
    float* mh  = reinterpret_cast<float*>(smem + SM_MH);
    int*   ptile = reinterpret_cast<int*>(smem + SM_PT);
    float* red = reinterpret_cast<float*>(smem + SM_RED);

    const int tid  = threadIdx.x;
    const int wid  = tid >> 5;
    const int lane = tid & 31;
    const int half = blockIdx.x & 1;               // which centroid half

    // ---- prologue: steal tile 0; load+convert this half's mu; m2 ----
    if (tid == 0) {
        unsigned t = atomicAdd(&g_tile2[half], 1u);
        ptile[0] = (t < (unsigned)ntiles) ? (int)t : -1;   // always valid (grid/2 << ntiles)
    }
    const float* muh = mu + (size_t)half * NLOC * KDIM;
    #pragma unroll
    for (int it = 0; it < 16; it++) {              // 4096 out-chunks of 16B
        int idx = tid + it * THREADS;
        int row = idx >> 4, kc = idx & 15;
        const float4* p = reinterpret_cast<const float4*>(muh + (size_t)row * KDIM + kc * 8);
        cvt_sts(p[0], p[1], smem + SM_MU + row * STRIDE_B + kc * 16);
    }
    __syncthreads();

    int t_cur = ptile[0];

    // prefetch z tile t_cur into registers (32 regs)
    float4 pf[8];
    {
        const size_t m0 = (size_t)t_cur * MT;
        #pragma unroll
        for (int it = 0; it < 4; it++) {
            int idx = tid + it * THREADS;
            int row = idx >> 4, kc = idx & 15;
            const float4* p = reinterpret_cast<const float4*>(z + (m0 + row) * KDIM + kc * 8);
            pf[2 * it]     = p[0];
            pf[2 * it + 1] = p[1];
        }
    }

    // m2 per local centroid from the f16 values (thread t -> centroid t)
    {
        float s = 0.0f;
        #pragma unroll
        for (int j = 0; j < 16; j++) {
            uint4 q = *reinterpret_cast<const uint4*>(smem + SM_MU + tid * STRIDE_B + j * 16);
            uint32_t u[4] = {q.x, q.y, q.z, q.w};
            #pragma unroll
            for (int e = 0; e < 4; e++) {
                float2 f = __half22float2(*reinterpret_cast<const __half2*>(&u[e]));
                s = fmaf(f.x, f.x, s);
                s = fmaf(f.y, f.y, s);
            }
        }
        m2s[tid] = s;
    }

    // per-warp constants for the GEMM
    const int tg = lane & 3;
    const int g  = lane >> 2;
    const int rw = wid & 3;            // row-group (m16): 4 groups cover 64 rows
    const int nh2 = wid >> 2;          // local n-half (0/1): 128 centroids each
    const int r0 = rw * 16;
    const int nbase = nh2 * 128;
    const uint32_t bb = sbase + SM_MU
                      + (lane & 7) * STRIDE_B
                      + (((lane >> 3) & 1) ? 16u : 0u)
                      + (lane >> 4) * 8 * STRIDE_B
                      + nbase * STRIDE_B;

    // ================= main loop =================
    for (int i = 0;; i++) {
        // a. store current tile (registers -> f16 smem)
        #pragma unroll
        for (int it = 0; it < 4; it++) {
            int idx = tid + it * THREADS;
            int row = idx >> 4, kc = idx & 15;
            cvt_sts(pf[2 * it], pf[2 * it + 1], smem + SM_Z + row * STRIDE_B + kc * 16);
        }
        // b. steal next tile (double-slot to avoid read/write race)
        if (tid == 0) {
            unsigned t = atomicAdd(&g_tile2[half], 1u);
            ptile[(i + 1) & 1] = (t < (unsigned)ntiles) ? (int)t : -1;
        }
        __syncthreads();                            // S1

        // d. issue next tile's loads early (hide DRAM latency under compute)
        const int t_next = ptile[(i + 1) & 1];
        if (t_next >= 0) {
            const size_t m0 = (size_t)t_next * MT;
            #pragma unroll
            for (int it = 0; it < 4; it++) {
                int idx = tid + it * THREADS;
                int row = idx >> 4, kc = idx & 15;
                const float4* p = reinterpret_cast<const float4*>(z + (m0 + row) * KDIM + kc * 8);
                pf[2 * it]     = p[0];
                pf[2 * it + 1] = p[1];
            }
        }

        // e. |z|^2: 2 threads per row, fp32 from the f16 values
        if (tid < 2 * MT) {
            const int row = tid >> 1;
            const int hk  = tid & 1;
            float s = 0.0f;
            #pragma unroll
            for (int j = 0; j < 8; j++) {
                uint4 q = *reinterpret_cast<const uint4*>(smem + SM_Z + row * STRIDE_B
                                                          + hk * 128 + j * 16);
                uint32_t u[4] = {q.x, q.y, q.z, q.w};
                #pragma unroll
                for (int e = 0; e < 4; e++) {
                    float2 f = __half22float2(*reinterpret_cast<const __half2*>(&u[e]));
                    s = fmaf(f.x, f.x, s);
                    s = fmaf(f.y, f.y, s);
                }
            }
            s += __shfl_xor_sync(0xffffffffu, s, 1);
            if (hk == 0) z2s[row] = s;
        }

        // f. GEMM: m16 per warp x 128 local centroids, f16 accum
        {
            uint32_t A[8][4];
            const uint32_t ab = sbase + SM_Z + (lane & 15) * STRIDE_B
                              + ((lane & 16) ? 16u : 0u) + r0 * STRIDE_B;
            #pragma unroll
            for (int kk = 0; kk < 8; kk++)
                ldsm_x4(A[kk][0], A[kk][1], A[kk][2], A[kk][3], ab + kk * 32);

            float mn[2] = {INFINITY, INFINITY};
            #pragma unroll 1
            for (int nt = 0; nt < 8; nt++) {
                uint32_t acc[2][2] = {{0u, 0u}, {0u, 0u}};
                const uint32_t ba = bb + nt * 16 * STRIDE_B;
                #pragma unroll
                for (int kk = 0; kk < 8; kk++) {
                    uint32_t b0, b1, b2, b3;
                    ldsm_x4(b0, b1, b2, b3, ba + kk * 32);
                    mma_f16(acc[0][0], acc[0][1], A[kk], b0, b1);
                    mma_f16(acc[1][0], acc[1][1], A[kk], b2, b3);
                }
                const int n0 = nbase + nt * 16;
                #pragma unroll
                for (int c = 0; c < 2; c++) {
                    float2 m = *reinterpret_cast<const float2*>(&m2s[n0 + 8 * c + 2 * tg]);
                    float2 f0 = __half22float2(*reinterpret_cast<const __half2*>(&acc[c][0]));
                    float2 f1 = __half22float2(*reinterpret_cast<const __half2*>(&acc[c][1]));
                    mn[0] = fminf(mn[0], fmaf(-2.0f, f0.x, m.x));
                    mn[0] = fminf(mn[0], fmaf(-2.0f, f0.y, m.y));
                    mn[1] = fminf(mn[1], fmaf(-2.0f, f1.x, m.x));
                    mn[1] = fminf(mn[1], fmaf(-2.0f, f1.y, m.y));
                }
            }
            #pragma unroll
            for (int q = 0; q < 2; q++) {
                mn[q] = fminf(mn[q], __shfl_xor_sync(0xffffffffu, mn[q], 1));
                mn[q] = fminf(mn[q], __shfl_xor_sync(0xffffffffu, mn[q], 2));
            }
            if (tg == 0) {
                mh[(r0 + g)     * 2 + nh2] = mn[0];
                mh[(r0 + g + 8) * 2 + nh2] = mn[1];
            }
        }
        __syncthreads();                            // S2

        // h. epilogue: combine local n-halves, encode, atomicMax into global
        if (tid < 2 * MT) {
            const int row = tid >> 1;
            const int h   = tid & 1;
            float v = mh[row * 2 + h];
            v = fminf(v, __shfl_xor_sync(0xffffffffu, v, 1));
            if (h == 0) {
                float d2 = fmaxf(z2s[row] + v, 0.0f);
                unsigned enc = ~__float_as_uint(d2);   // min d2 <=> max enc; identity 0
                atomicMax(&g_enc[t_cur * MT + row], enc);
            }
        }
        __syncthreads();                            // S3

        t_cur = t_next;
        if (t_cur < 0) break;
    }

    // ================= phase 2: grid-wide combine =================
    __threadfence();
    if (tid == 0) {
        atomicAdd(&g_cnt, 1u);
        volatile unsigned int* vc = &g_cnt;
        while (*vc < (unsigned)grid) __nanosleep(64);
    }
    __syncthreads();

    // sliced sqrt + sum; self-clean g_enc
    const int slice = (L + grid - 1) / grid;
    const int base  = blockIdx.x * slice;
    float d = 0.0f;
    for (int idx = base + tid; idx < base + slice && idx < L; idx += THREADS) {
        unsigned u = g_enc[idx];
        g_enc[idx] = 0u;
        d += sqrtf(__uint_as_float(~u));
    }
    #pragma unroll
    for (int o = 16; o > 0; o >>= 1) d += __shfl_down_sync(0xffffffffu, d, o);
    if (lane == 0) red[wid] = d;
    __syncthreads();
    if (tid == 0) {
        float s = red[0] + red[1] + red[2] + red[3]
                + red[4] + red[5] + red[6] + red[7];
        atomicAdd(&g_sum, s);
        __threadfence();
        unsigned c = atomicAdd(&g_cnt2, 1u);
        if (c == (unsigned)(grid - 1)) {
            out[0] = (*(volatile float*)&g_sum) / (float)L;
            g_sum = 0.0f;
            g_cnt = 0u;
            g_cnt2 = 0u;
            g_tile2[0] = 0u;
            g_tile2[1] = 0u;
        }
    }
}

extern "C" void kernel_launch(void* const* d_in, const int* in_sizes, int n_in,
                              void* d_out, int out_size) {
    const float* z  = (const float*)d_in[0];
    const float* mu = (const float*)d_in[1];
    float* out = (float*)d_out;

    int L = in_sizes[0] / KDIM;   // 65536
    int ntiles = L / MT;          // 1024

    static int nsm = 0;
    if (nsm == 0) {
        cudaDeviceGetAttribute(&nsm, cudaDevAttrMultiProcessorCount, 0);
        cudaFuncSetAttribute(km_main, cudaFuncAttributeMaxDynamicSharedMemorySize, SMEM_BYTES);
    }
    int grid = 2 * nsm;           // 2 CTAs per SM (one per centroid half)

    km_main<<<grid, THREADS, SMEM_BYTES>>>(z, mu, out, L, ntiles, grid);
}

// round 16
// speedup vs baseline: 1.0494x; 1.0494x over previous
#include <cuda_runtime.h>
#include <cuda_fp16.h>
#include <cstdint>
#include <math.h>

// KMeansClusteringLoss, R13: chain-maximized HMMA (32 indep accum chains/SMSP).
//   cost(l,c) = |mu_c|^2 - 2 <z_l, mu_c>,  d(l) = sqrt(max(|z_l|^2 + min_c cost, 0))
//   out = mean_l d(l)
//
// 512 threads, 16 warps, no warp specialization. MT=64 z tile. Per warp:
// m32 x n64, inner n32 with 8 independent f16-accumulator chains. Next z tile
// is LDG-prefetched into registers before the GEMM and stored at loop top.

#define KDIM  128
#define CDIM  512
#define MT    64
#define THREADS 512

#define STRIDE_B 272       // 128 f16 (256B) + 16B pad -> conflict-free LDSM

// dynamic smem layout (bytes)
#define SM_MU   0                           // 512 x 272 = 139264
#define SM_Z    139264                      // 64 x 272 = 17408
#define SM_M2   156672                      // 512 f32
#define SM_Z2   158720                      // 64 f32
#define SM_MH   158976                      // 64 x 8 f32
#define SM_PT   161024                      // 2 ints
#define SM_RED  161032                      // 2 f32
#define SMEM_BYTES 161088

__device__ float g_sum;                    // zero-init; self-cleaned
__device__ unsigned int g_cnt;
__device__ unsigned int g_tile;

// ---------------- helpers ----------------
__device__ __forceinline__ uint32_t smem_u32(const void* p) {
    uint32_t a;
    asm("{ .reg .u64 t; cvta.to.shared.u64 t, %1; cvt.u32.u64 %0, t; }" : "=r"(a) : "l"(p));
    return a;
}
__device__ __forceinline__ void ldsm_x4(uint32_t& r0, uint32_t& r1, uint32_t& r2, uint32_t& r3,
                                        uint32_t addr) {
    asm volatile("ldmatrix.sync.aligned.m8n8.x4.shared.b16 {%0,%1,%2,%3}, [%4];"
                 : "=r"(r0), "=r"(r1), "=r"(r2), "=r"(r3) : "r"(addr));
}
// f16 x f16 -> f16 accum. d0 = (row g, cols 2tg..), d1 = (row g+8).
__device__ __forceinline__ void mma_f16(uint32_t& d0, uint32_t& d1, const uint32_t* a,
                                        uint32_t b0, uint32_t b1) {
    asm volatile(
        "mma.sync.aligned.m16n8k16.row.col.f16.f16.f16.f16 "
        "{%0,%1}, {%2,%3,%4,%5}, {%6,%7}, {%0,%1};"
        : "+r"(d0), "+r"(d1)
        : "r"(a[0]), "r"(a[1]), "r"(a[2]), "r"(a[3]), "r"(b0), "r"(b1));
}
__device__ __forceinline__ void cvt_sts(const float4& v0, const float4& v1, char* dst) {
    __half2 h0 = __floats2half2_rn(v0.x, v0.y);
    __half2 h1 = __floats2half2_rn(v0.z, v0.w);
    __half2 h2 = __floats2half2_rn(v1.x, v1.y);
    __half2 h3 = __floats2half2_rn(v1.z, v1.w);
    uint4 q;
    q.x = *reinterpret_cast<uint32_t*>(&h0);
    q.y = *reinterpret_cast<uint32_t*>(&h1);
    q.z = *reinterpret_cast<uint32_t*>(&h2);
    q.w = *reinterpret_cast<uint32_t*>(&h3);
    *reinterpret_cast<uint4*>(dst) = q;
}

// ---------------- persistent kernel ----------------
__global__ void __launch_bounds__(THREADS, 1) km_main(
    const float* __restrict__ z, const float* __restrict__ mu,
    float* __restrict__ out, int L, int ntiles, int grid)
{
    extern __shared__ char smem[];
    const uint32_t sbase = smem_u32(smem);
    float* m2s = reinterpret_cast<float*>(smem + SM_M2);
    float* z2s = reinterpret_cast<float*>(smem + SM_Z2);
    float* mh  = reinterpret_cast<float*>(smem + SM_MH);    // [row][8 n-groups]
    int*   ptile = reinterpret_cast<int*>(smem + SM_PT);
    float* red = reinterpret_cast<float*>(smem + SM_RED);

    const int tid  = threadIdx.x;
    const int wid  = tid >> 5;
    const int lane = tid & 31;

    // ---- prologue: steal tile 0; mu fp32->fp16 into smem; m2 ----
    if (tid == 0) ptile[0] = (int)atomicAdd(&g_tile, 1u);   // grid <= ntiles

    #pragma unroll
    for (int it = 0; it < 16; it++) {              // 8192 chunks of 16B out
        int idx = tid + it * THREADS;
        int row = idx >> 4, kc = idx & 15;
        const float4* p = reinterpret_cast<const float4*>(mu + (size_t)row * KDIM + kc * 8);
        cvt_sts(p[0], p[1], smem + SM_MU + row * STRIDE_B + kc * 16);
    }
    __syncthreads();

    // m2 per centroid from the f16 values (thread t -> centroid t)
    {
        float s = 0.0f;
        #pragma unroll
        for (int j = 0; j < 16; j++) {
            uint4 q = *reinterpret_cast<const uint4*>(smem + SM_MU + tid * STRIDE_B + j * 16);
            uint32_t u[4] = {q.x, q.y, q.z, q.w};
            #pragma unroll
            for (int e = 0; e < 4; e++) {
                float2 f = __half22float2(*reinterpret_cast<const __half2*>(&u[e]));
                s = fmaf(f.x, f.x, s);
                s = fmaf(f.y, f.y, s);
            }
        }
        m2s[tid] = s;
    }

    int t_cur = ptile[0];

    // prefetch z tile t_cur into registers (64 rows x 128 f32 / 512 thr = 16 f32)
    float4 pf[4];
    {
        const size_t m0 = (size_t)t_cur * MT;
        #pragma unroll
        for (int it = 0; it < 2; it++) {
            int idx = tid + it * THREADS;
            int row = idx >> 4, kc = idx & 15;
            const float4* p = reinterpret_cast<const float4*>(z + (m0 + row) * KDIM + kc * 8);
            pf[2 * it]     = p[0];
            pf[2 * it + 1] = p[1];
        }
    }

    // per-warp GEMM constants
    const int tg = lane & 3;
    const int g  = lane >> 2;
    const int rw = wid & 1;            // row-group (m32): 2 groups cover 64 rows
    const int nq = wid >> 1;           // n-group (0..7): 64 centroids each
    const int r0 = rw * 32;
    const int nbase = nq * 64;
    const uint32_t bb = sbase + SM_MU
                      + (lane & 7) * STRIDE_B
                      + (((lane >> 3) & 1) ? 16u : 0u)
                      + (lane >> 4) * 8 * STRIDE_B
                      + nbase * STRIDE_B;
    const uint32_t ab0 = sbase + SM_Z + (lane & 15) * STRIDE_B
                       + ((lane & 16) ? 16u : 0u) + r0 * STRIDE_B;

    // ================= main loop =================
    for (int i = 0;; i++) {
        // a. store current tile (registers -> f16 smem)
        #pragma unroll
        for (int it = 0; it < 2; it++) {
            int idx = tid + it * THREADS;
            int row = idx >> 4, kc = idx & 15;
            cvt_sts(pf[2 * it], pf[2 * it + 1], smem + SM_Z + row * STRIDE_B + kc * 16);
        }
        // b. steal next tile (alternating slot)
        if (tid == 0) {
            unsigned t = atomicAdd(&g_tile, 1u);
            ptile[(i + 1) & 1] = (t < (unsigned)ntiles) ? (int)t : -1;
        }
        __syncthreads();                            // S1

        // c. issue next tile's LDG early (lands during GEMM)
        const int t_next = ptile[(i + 1) & 1];
        if (t_next >= 0) {
            const size_t m0 = (size_t)t_next * MT;
            #pragma unroll
            for (int it = 0; it < 2; it++) {
                int idx = tid + it * THREADS;
                int row = idx >> 4, kc = idx & 15;
                const float4* p = reinterpret_cast<const float4*>(z + (m0 + row) * KDIM + kc * 8);
                pf[2 * it]     = p[0];
                pf[2 * it + 1] = p[1];
            }
        }

        // d. |z|^2: 2 threads per row (threads 0-127), fp32 from f16 values
        if (tid < 2 * MT) {
            const int row = tid >> 1;
            const int hk  = tid & 1;
            float s = 0.0f;
            #pragma unroll
            for (int j = 0; j < 8; j++) {
                uint4 q = *reinterpret_cast<const uint4*>(smem + SM_Z + row * STRIDE_B
                                                          + hk * 128 + j * 16);
                uint32_t u[4] = {q.x, q.y, q.z, q.w};
                #pragma unroll
                for (int e = 0; e < 4; e++) {
                    float2 f = __half22float2(*reinterpret_cast<const __half2*>(&u[e]));
                    s = fmaf(f.x, f.x, s);
                    s = fmaf(f.y, f.y, s);
                }
            }
            s += __shfl_xor_sync(0xffffffffu, s, 1);
            if (hk == 0) z2s[row] = s;
        }

        // e. GEMM: m32 x n64 per warp, inner n32 with 8 indep f16 chains
        {
            uint32_t A[2][8][4];                     // 64 regs
            #pragma unroll
            for (int rg = 0; rg < 2; rg++)
                #pragma unroll
                for (int kk = 0; kk < 8; kk++)
                    ldsm_x4(A[rg][kk][0], A[rg][kk][1], A[rg][kk][2], A[rg][kk][3],
                            ab0 + rg * 16 * STRIDE_B + kk * 32);

            float mn[4] = {INFINITY, INFINITY, INFINITY, INFINITY};
            #pragma unroll 1
            for (int nt = 0; nt < 2; nt++) {         // 2 iters of n32
                uint32_t acc[2][4][2];               // [rg][n8 chunk][2 regs] - 8 chains
                #pragma unroll
                for (int rg = 0; rg < 2; rg++)
                    #pragma unroll
                    for (int c = 0; c < 4; c++)
                        acc[rg][c][0] = acc[rg][c][1] = 0u;

                const uint32_t ba = bb + nt * 32 * STRIDE_B;
                #pragma unroll
                for (int kk = 0; kk < 8; kk++) {
                    uint32_t b0, b1, b2, b3, b4, b5, b6, b7;
                    ldsm_x4(b0, b1, b2, b3, ba + kk * 32);
                    ldsm_x4(b4, b5, b6, b7, ba + 16 * STRIDE_B + kk * 32);
                    mma_f16(acc[0][0][0], acc[0][0][1], A[0][kk], b0, b1);
                    mma_f16(acc[0][1][0], acc[0][1][1], A[0][kk], b2, b3);
                    mma_f16(acc[0][2][0], acc[0][2][1], A[0][kk], b4, b5);
                    mma_f16(acc[0][3][0], acc[0][3][1], A[0][kk], b6, b7);
                    mma_f16(acc[1][0][0], acc[1][0][1], A[1][kk], b0, b1);
                    mma_f16(acc[1][1][0], acc[1][1][1], A[1][kk], b2, b3);
                    mma_f16(acc[1][2][0], acc[1][2][1], A[1][kk], b4, b5);
                    mma_f16(acc[1][3][0], acc[1][3][1], A[1][kk], b6, b7);
                }
                const int n0 = nbase + nt * 32;
                #pragma unroll
                for (int c = 0; c < 4; c++) {
                    float2 m = *reinterpret_cast<const float2*>(&m2s[n0 + 8 * c + 2 * tg]);
                    #pragma unroll
                    for (int rg = 0; rg < 2; rg++) {
                        float2 f0 = __half22float2(*reinterpret_cast<const __half2*>(&acc[rg][c][0]));
                        float2 f1 = __half22float2(*reinterpret_cast<const __half2*>(&acc[rg][c][1]));
                        mn[rg * 2 + 0] = fminf(mn[rg * 2 + 0], fmaf(-2.0f, f0.x, m.x));
                        mn[rg * 2 + 0] = fminf(mn[rg * 2 + 0], fmaf(-2.0f, f0.y, m.y));
                        mn[rg * 2 + 1] = fminf(mn[rg * 2 + 1], fmaf(-2.0f, f1.x, m.x));
                        mn[rg * 2 + 1] = fminf(mn[rg * 2 + 1], fmaf(-2.0f, f1.y, m.y));
                    }
                }
            }
            #pragma unroll
            for (int q = 0; q < 4; q++) {
                mn[q] = fminf(mn[q], __shfl_xor_sync(0xffffffffu, mn[q], 1));
                mn[q] = fminf(mn[q], __shfl_xor_sync(0xffffffffu, mn[q], 2));
            }
            if (tg == 0) {
                mh[(r0 + g)      * 8 + nq] = mn[0];
                mh[(r0 + g + 8)  * 8 + nq] = mn[1];
                mh[(r0 + g + 16) * 8 + nq] = mn[2];
                mh[(r0 + g + 24) * 8 + nq] = mn[3];
            }
        }
        __syncthreads();                            // S2

        // f. epilogue: threads 0-63, min over 8 n-groups, sqrt, warp sums
        if (tid < MT) {
            float v = INFINITY;
            #pragma unroll
            for (int j = 0; j < 8; j++) v = fminf(v, mh[tid * 8 + j]);
            float d = sqrtf(fmaxf(z2s[tid] + v, 0.0f));
            #pragma unroll
            for (int o = 16; o > 0; o >>= 1) d += __shfl_down_sync(0xffffffffu, d, o);
            if (lane == 0) red[wid] = d;
        }
        __syncthreads();                            // S3
        if (tid == 0) atomicAdd(&g_sum, red[0] + red[1]);

        t_cur = t_next;
        if (t_cur < 0) break;
    }

    // ---- finalize: last CTA writes the mean and self-cleans globals ----
    __syncthreads();
    if (tid == 0) {
        __threadfence();
        unsigned int c = atomicAdd(&g_cnt, 1u);
        if (c == (unsigned int)(grid - 1)) {
            out[0] = (*(volatile float*)&g_sum) / (float)L;
            g_sum = 0.0f;
            g_cnt = 0u;
            g_tile = 0u;
        }
    }
}

extern "C" void kernel_launch(void* const* d_in, const int* in_sizes, int n_in,
                              void* d_out, int out_size) {
    const float* z  = (const float*)d_in[0];
    const float* mu = (const float*)d_in[1];
    float* out = (float*)d_out;

    int L = in_sizes[0] / KDIM;   // 65536
    int ntiles = L / MT;          // 1024

    static int nsm = 0;
    if (nsm == 0) {
        cudaDeviceGetAttribute(&nsm, cudaDevAttrMultiProcessorCount, 0);
        cudaFuncSetAttribute(km_main, cudaFuncAttributeMaxDynamicSharedMemorySize, SMEM_BYTES);
    }
    int grid = (ntiles < nsm) ? ntiles : nsm;

    km_main<<<grid, THREADS, SMEM_BYTES>>>(z, mu, out, L, ntiles, grid);
}